// round 9
// baseline (speedup 1.0000x reference)
#include <cuda_runtime.h>

// Fused local NCC loss (kernel=3, zero 'same' padding) over 192^3 f32 volumes.
// Each warp owns ONE 64-wide d-chunk (s = threadIdx.y in {0,1,2}), one h row
// (tz = threadIdx.z), marching w. Lane owns f32x2 pack d=(64s+2l, 64s+2l+1).
// Rows h-1,h,h+1 via per-row pointers (zero-buffer redirect at h edges).
// w-window: 3 plane buffers whose sum is the current window; oldest rebuilt
// in place each step. d-window: in-warp shuffles; chunk-boundary elements
// exchanged via a tiny double-buffered smem table + 1 bar per step.

#define SZ    192
#define SZ2   (SZ * SZ)
#define NTOT  (SZ * SZ * SZ)
#define WCHUNK 16
#define GY     96              // 192 h rows / 2 rows per block
#define GZ     12              // 192 / WCHUNK
#define NBLK   (GY * GZ)       // 1152

typedef unsigned long long u64;

__device__ float        g_zero[4608];          // static zero (BSS) pad source
__device__ float        g_partial[NBLK];
__device__ unsigned int g_count = 0;

__device__ __forceinline__ void upk2(u64 v, float& lo, float& hi) {
    asm("mov.b64 {%0, %1}, %2;" : "=f"(lo), "=f"(hi) : "l"(v));
}
__device__ __forceinline__ u64 add2(u64 a, u64 b) {
    u64 r; asm("add.rn.f32x2 %0, %1, %2;" : "=l"(r) : "l"(a), "l"(b)); return r;
}
__device__ __forceinline__ u64 mul2(u64 a, u64 b) {
    u64 r; asm("mul.rn.f32x2 %0, %1, %2;" : "=l"(r) : "l"(a), "l"(b)); return r;
}
__device__ __forceinline__ u64 fma2(u64 a, u64 b, u64 c) {
    u64 r; asm("fma.rn.f32x2 %0, %1, %2, %3;" : "=l"(r) : "l"(a), "l"(b), "l"(c)); return r;
}

// h-summed plane components {I,J,II,JJ,IJ} for this warp's pack column.
__device__ __forceinline__ void build5(u64 (&P)[5],
    u64 I0, u64 I1, u64 I2, u64 J0, u64 J1, u64 J2)
{
    P[0] = add2(add2(I0, I1), I2);
    P[1] = add2(add2(J0, J1), J2);
    u64 a = mul2(I0, I0); a = fma2(I1, I1, a); a = fma2(I2, I2, a); P[2] = a;
    a = mul2(J0, J0); a = fma2(J1, J1, a); a = fma2(J2, J2, a); P[3] = a;
    a = mul2(I0, J0); a = fma2(I1, J1, a); a = fma2(I2, J2, a); P[4] = a;
}

__device__ __forceinline__ float ncc1(float sI, float sJ, float sII, float sJJ, float sIJ)
{
    const float ninv = -1.0f / 27.0f;
    float m1 = sI * ninv;
    float m2 = sJ * ninv;
    float cr = fmaf(m2, sI, sIJ);     // sum((I-uI)(J-uJ))
    float Iv = fmaf(m1, sI, sII);     // sum((I-uI)^2)
    float Jv = fmaf(m2, sJ, sJJ);     // sum((J-uJ)^2)
    return __fdividef(cr * cr, fmaf(Iv, Jv, 1e-5f));
}

__global__ __launch_bounds__(192, 4)
void lncc_fused_kernel(const float* __restrict__ pred,
                       const float* __restrict__ targ,
                       float* __restrict__ out)
{
    const int lane = threadIdx.x;                  // 0..31
    const int s    = threadIdx.y;                  // 0..2 d-chunk
    const int tz   = threadIdx.z;                  // 0..1 h row in block
    const int h    = blockIdx.y * 2 + tz;
    const int w0   = blockIdx.z * WCHUNK;
    const int db   = 64 * s + 2 * lane;            // first d element of pack

    // [parity][tz][s][side 0=lo(d=64s) 1=hi(d=64s+63)][comp]
    __shared__ float sm[2][2][3][2][5];

    // Per-row pointers (positioned at plane w0-1); h-edge rows -> zero buffer.
    const float* pI[3];
    const float* pJ[3];
    #pragma unroll
    for (int r = 0; r < 3; r++) {
        int hh = h - 1 + r;
        bool ok = (hh >= 0) && (hh < SZ);
        long off = (long)hh * SZ2 + (long)(w0 - 1) * SZ + db;
        pI[r] = ok ? pred + off : g_zero + db;
        pJ[r] = ok ? targ + off : g_zero + db;
    }

    u64 P[3][5];
    {   // prologue: planes w0-1 (zeros at volume edge), w0, w0+1
        u64 I0 = 0, I1 = 0, I2 = 0, J0 = 0, J1 = 0, J2 = 0;
        if (w0 >= 1) {
            I0 = *(const u64*)(pI[0]); J0 = *(const u64*)(pJ[0]);
            I1 = *(const u64*)(pI[1]); J1 = *(const u64*)(pJ[1]);
            I2 = *(const u64*)(pI[2]); J2 = *(const u64*)(pJ[2]);
        }
        build5(P[0], I0, I1, I2, J0, J1, J2);
        I0 = *(const u64*)(pI[0] + SZ); J0 = *(const u64*)(pJ[0] + SZ);
        I1 = *(const u64*)(pI[1] + SZ); J1 = *(const u64*)(pJ[1] + SZ);
        I2 = *(const u64*)(pI[2] + SZ); J2 = *(const u64*)(pJ[2] + SZ);
        build5(P[1], I0, I1, I2, J0, J1, J2);
        I0 = *(const u64*)(pI[0] + 2 * SZ); J0 = *(const u64*)(pJ[0] + 2 * SZ);
        I1 = *(const u64*)(pI[1] + 2 * SZ); J1 = *(const u64*)(pJ[1] + 2 * SZ);
        I2 = *(const u64*)(pI[2] + 2 * SZ); J2 = *(const u64*)(pJ[2] + 2 * SZ);
        build5(P[2], I0, I1, I2, J0, J1, J2);
    }
    #pragma unroll
    for (int r = 0; r < 3; r++) { pI[r] += 3 * SZ; pJ[r] += 3 * SZ; }

    float acc = 0.f;
    int kk = 0;
    int wnext = w0 + 2;

    // Window sums + seam + NCC, shared by pipelined and final steps.
#define SEAM_NCC(OLD, A, B)                                                   \
    float lo[5], hi[5];                                                       \
    {                                                                         \
        _Pragma("unroll")                                                     \
        for (int c = 0; c < 5; c++) {                                         \
            u64 W = add2(add2(P[OLD][c], P[A][c]), P[B][c]);                  \
            upk2(W, lo[c], hi[c]);                                            \
        }                                                                     \
    }                                                                         \
    const int par = kk & 1;                                                   \
    if (lane == 0) {                                                          \
        _Pragma("unroll")                                                     \
        for (int c = 0; c < 5; c++) sm[par][tz][s][0][c] = lo[c];             \
    }                                                                         \
    if (lane == 31) {                                                         \
        _Pragma("unroll")                                                     \
        for (int c = 0; c < 5; c++) sm[par][tz][s][1][c] = hi[c];             \
    }

#define SEAM_FINISH()                                                         \
    float prev[5], nxt[5];                                                    \
    {                                                                         \
        _Pragma("unroll")                                                     \
        for (int c = 0; c < 5; c++) {                                         \
            prev[c] = __shfl_up_sync(0xffffffffu, hi[c], 1);                  \
            nxt[c]  = __shfl_down_sync(0xffffffffu, lo[c], 1);                \
        }                                                                     \
        if (lane == 0) {                                                      \
            _Pragma("unroll")                                                 \
            for (int c = 0; c < 5; c++)                                       \
                prev[c] = s ? sm[par][tz][s - 1][1][c] : 0.f;                 \
        }                                                                     \
        if (lane == 31) {                                                     \
            _Pragma("unroll")                                                 \
            for (int c = 0; c < 5; c++)                                       \
                nxt[c] = (s < 2) ? sm[par][tz][s + 1][0][c] : 0.f;            \
        }                                                                     \
        float t0 = lo[0] + hi[0], t1 = lo[1] + hi[1], t2 = lo[2] + hi[2];     \
        float t3 = lo[3] + hi[3], t4 = lo[4] + hi[4];                         \
        acc += ncc1(t0 + prev[0], t1 + prev[1], t2 + prev[2],                 \
                    t3 + prev[3], t4 + prev[4]);                              \
        acc += ncc1(t0 + nxt[0],  t1 + nxt[1],  t2 + nxt[2],                  \
                    t3 + nxt[3],  t4 + nxt[4]);                               \
    }

    // Pipelined step: next-plane loads issued before the bar.
#define STEP(OLD, A, B) do {                                                  \
        SEAM_NCC_HDR_##OLD:;                                                  \
        SEAM_NCC(OLD, A, B)                                                   \
        u64 I0 = 0, I1 = 0, I2 = 0, J0 = 0, J1 = 0, J2 = 0;                   \
        if (wnext < SZ) {                                                     \
            I0 = *(const u64*)(pI[0]); J0 = *(const u64*)(pJ[0]);             \
            I1 = *(const u64*)(pI[1]); J1 = *(const u64*)(pJ[1]);             \
            I2 = *(const u64*)(pI[2]); J2 = *(const u64*)(pJ[2]);             \
        }                                                                     \
        __syncthreads();                                                      \
        SEAM_FINISH()                                                         \
        build5(P[OLD], I0, I1, I2, J0, J1, J2);                               \
        _Pragma("unroll")                                                     \
        for (int r = 0; r < 3; r++) { pI[r] += SZ; pJ[r] += SZ; }             \
        wnext++; kk++;                                                        \
    } while (0)

    #pragma unroll 1
    for (int t = 0; t < 5; t++) {
        { STEP(0, 1, 2); }
        { STEP(1, 2, 0); }
        { STEP(2, 0, 1); }
    }
    {   // final emit (w = w0+15): no loads, no rebuild
        SEAM_NCC(0, 1, 2)
        __syncthreads();
        SEAM_FINISH()
    }
#undef STEP
#undef SEAM_NCC
#undef SEAM_FINISH

    // ---- deterministic in-kernel reduction ----
    __shared__ float  sred[192];
    __shared__ double dred[192];
    __shared__ unsigned int s_last;
    const int tid = lane + 32 * s + 96 * tz;   // 0..191

    sred[tid] = acc;
    __syncthreads();
    if (tid < 64) sred[tid] += sred[tid + 64] + sred[tid + 128];
    __syncthreads();
    #pragma unroll
    for (int k = 32; k > 0; k >>= 1) {
        if (tid < k) sred[tid] += sred[tid + k];
        __syncthreads();
    }
    if (tid == 0) {
        const int blin = blockIdx.y + GY * blockIdx.z;
        g_partial[blin] = sred[0];
        __threadfence();
        unsigned old = atomicAdd(&g_count, 1u);
        s_last = (old == (unsigned)(NBLK - 1)) ? 1u : 0u;
    }
    __syncthreads();

    if (s_last) {
        double v = 0.0;
        for (int i = tid; i < NBLK; i += 192)
            v += (double)g_partial[i];
        dred[tid] = v;
        __syncthreads();
        if (tid < 64) dred[tid] += dred[tid + 64] + dred[tid + 128];
        __syncthreads();
        #pragma unroll
        for (int k = 32; k > 0; k >>= 1) {
            if (tid < k) dred[tid] += dred[tid + k];
            __syncthreads();
        }
        if (tid == 0) {
            out[0] = (float)(-dred[0] / (double)NTOT);
            g_count = 0;   // reset for the next (graph-replayed) call
        }
    }
}

extern "C" void kernel_launch(void* const* d_in, const int* in_sizes, int n_in,
                              void* d_out, int out_size) {
    const float* pred = (const float*)d_in[0];
    const float* targ = (const float*)d_in[1];
    dim3 grid(1, GY, GZ);
    dim3 block(32, 3, 2);
    lncc_fused_kernel<<<grid, block>>>(pred, targ, (float*)d_out);
}